// round 9
// baseline (speedup 1.0000x reference)
#include <cuda_runtime.h>
#include <cuda_bf16.h>
#include <math.h>

// Problem constants
#define BB 64
#define TT 1000
#define NN 512
#define G3 1536
#define GRID_SCAN 128
#define SCAN_THREADS 512

// ---------------------------------------------------------------------------
// f32x2 packed-FMA helpers (PTX-only; ptxas never auto-fuses)
// ---------------------------------------------------------------------------
__device__ __forceinline__ unsigned long long dup2(float x) {
    unsigned long long r;
    asm("mov.b64 %0, {%1, %1};" : "=l"(r) : "f"(x));
    return r;
}
__device__ __forceinline__ void fma2(unsigned long long& d,
                                     unsigned long long a,
                                     unsigned long long b) {
    asm("fma.rn.f32x2 %0, %1, %2, %0;" : "+l"(d) : "l"(a), "l"(b));
}
__device__ __forceinline__ float2 unpack2(unsigned long long v) {
    float2 f;
    asm("mov.b64 {%0, %1}, %2;" : "=f"(f.x), "=f"(f.y) : "l"(v));
    return f;
}

// ---------------------------------------------------------------------------
// Scratch. Barrier counter and generation flag on SEPARATE 128B L2 lines.
// ---------------------------------------------------------------------------
struct __align__(128) Pad128 { unsigned v; unsigned pad[31]; };
__device__ Pad128   g_count;                        // arrivals (RMW line)
__device__ Pad128   g_gen;                          // generation (read-mostly line)
__device__ float    g_xproj[(size_t)BB * TT * G3];  // [B][T][3N]
__device__ float    g_ht[2][NN * BB];               // transposed hidden [k][b]

// ---------------------------------------------------------------------------
// Kernel 1: x_proj = h_enc @ W_ih^T + b_ih. 128x128x16 tiles, 8x8 microtile,
// f32x2-packed j. Block (0,0) also resets barrier + zeroes h0 (every replay).
// ---------------------------------------------------------------------------
__global__ void __launch_bounds__(256) xproj_kernel(
    const float* __restrict__ A,     // [64000][512]
    const float* __restrict__ Wih,   // [1536][512]
    const float* __restrict__ bih,   // [1536]
    float* __restrict__ C)           // [64000][1536]
{
    __shared__ float As[16][128];
    __shared__ float Bs[16][128];

    const int tid   = threadIdx.x;
    const int mBase = blockIdx.y * 128;
    const int nBase = blockIdx.x * 128;
    const int tx = tid & 15;
    const int ty = tid >> 4;

    if (blockIdx.x == 0 && blockIdx.y == 0) {
        if (tid == 0) { g_count.v = 0u; g_gen.v = 0u; }
        for (int j = tid; j < NN * BB; j += 256) g_ht[0][j] = 0.0f;
    }

    unsigned long long acc2[8][4];
#pragma unroll
    for (int i = 0; i < 8; i++)
#pragma unroll
        for (int j = 0; j < 4; j++) acc2[i][j] = 0ull;

    const int lr = tid >> 2;
    const int lk = (tid & 3) << 2;
    const float* Aptr = A   + (size_t)(mBase + lr) * NN + lk;
    const float* Bptr = Wih + (size_t)(nBase + lr) * NN + lk;

    for (int kt = 0; kt < NN; kt += 16) {
        const float4 a0 = *(const float4*)(Aptr + kt);
        const float4 a1 = *(const float4*)(Aptr + 64 * NN + kt);
        const float4 b0 = *(const float4*)(Bptr + kt);
        const float4 b1 = *(const float4*)(Bptr + 64 * NN + kt);
        __syncthreads();
        As[lk + 0][lr] = a0.x; As[lk + 1][lr] = a0.y; As[lk + 2][lr] = a0.z; As[lk + 3][lr] = a0.w;
        As[lk + 0][64 + lr] = a1.x; As[lk + 1][64 + lr] = a1.y; As[lk + 2][64 + lr] = a1.z; As[lk + 3][64 + lr] = a1.w;
        Bs[lk + 0][lr] = b0.x; Bs[lk + 1][lr] = b0.y; Bs[lk + 2][lr] = b0.z; Bs[lk + 3][lr] = b0.w;
        Bs[lk + 0][64 + lr] = b1.x; Bs[lk + 1][64 + lr] = b1.y; Bs[lk + 2][64 + lr] = b1.z; Bs[lk + 3][64 + lr] = b1.w;
        __syncthreads();
#pragma unroll
        for (int k = 0; k < 16; k++) {
            float af[8];
            *(float4*)&af[0] = *(const float4*)&As[k][ty * 4];
            *(float4*)&af[4] = *(const float4*)&As[k][64 + ty * 4];
            unsigned long long b2[4];
            *(uint4*)&b2[0] = *(const uint4*)&Bs[k][tx * 4];
            *(uint4*)&b2[2] = *(const uint4*)&Bs[k][64 + tx * 4];
#pragma unroll
            for (int i = 0; i < 8; i++) {
                const unsigned long long ad = dup2(af[i]);
#pragma unroll
                for (int j = 0; j < 4; j++) fma2(acc2[i][j], ad, b2[j]);
            }
        }
    }

    float bias[8];
#pragma unroll
    for (int j = 0; j < 8; j++) {
        int col = nBase + ((j < 4) ? (tx * 4 + j) : (64 + tx * 4 + (j - 4)));
        bias[j] = __ldg(&bih[col]);
    }
#pragma unroll
    for (int i = 0; i < 8; i++) {
        float a[8];
#pragma unroll
        for (int j = 0; j < 4; j++) {
            const float2 v = unpack2(acc2[i][j]);
            a[2 * j] = v.x; a[2 * j + 1] = v.y;
        }
        int row = mBase + ((i < 4) ? (ty * 4 + i) : (64 + ty * 4 + (i - 4)));
        float* cp = C + (size_t)row * G3 + nBase;
        *(float4*)(cp + tx * 4) =
            make_float4(a[0] + bias[0], a[1] + bias[1], a[2] + bias[2], a[3] + bias[3]);
        *(float4*)(cp + 64 + tx * 4) =
            make_float4(a[4] + bias[4], a[5] + bias[5], a[6] + bias[6], a[7] + bias[7]);
    }
}

// ---------------------------------------------------------------------------
// Kernel 2: persistent cooperative GRU scan.
//   128 CTAs x 512 threads (16 warps/SM, occ 25%). thread=(kq 0..7, nn 0..3,
//   b4 0..15): 64-k chunk, one n-col, 4 batches, f32x2 -> 6 FFMA2/k.
//   h READS: plain L1-cached (4x nn-broadcast reuse); refreshed once/step by
//   the acquire __threadfence after the grid barrier.
//   h WRITES: __stcg (L2-direct); release ordering via acq_rel arrival.
//   x_t: double-buffered in SMEM, prefetched for t+1 during the barrier wait.
// ---------------------------------------------------------------------------
__global__ void __launch_bounds__(SCAN_THREADS) gru_scan_kernel(
    const float* __restrict__ Whh,   // [1536][512]
    const float* __restrict__ bhh,   // [1536]
    float* __restrict__ out)         // [B][T][N]
{
    __shared__ float ws[12][520];          // W_hh slice: [gate*4+jn][k] (~25KB)
    __shared__ float xs[2][3][4][64];      // x_t double buffer: [par][gate][nn][b]
    __shared__ float red[8][3][4][64];     // partials: [kq][gate][nn][b] (24KB)
    __shared__ float hs[4][64];            // h_new: [nn][b]

    const int tid = threadIdx.x;
    const int n0  = blockIdx.x * 4;
    const int kq  = tid >> 6;          // 0..7 (64-k chunk)
    const int nn  = (tid >> 4) & 3;    // 0..3
    const int b4  = tid & 15;          // 4-batch group

    // Load W_hh slice once (un-duplicated; dup happens in-loop on alu pipe)
    for (int i = tid; i < 12 * 512; i += SCAN_THREADS) {
        const int row = i >> 9;            // gate*4 + jn
        const int k   = i & 511;
        const int gate = row >> 2;
        const int jn   = row & 3;
        ws[row][k] = __ldg(&Whh[(size_t)(gate * NN + n0 + jn) * NN + k]);
    }

    // Epilogue biases (tid<256: en = tid>>6)
    float bhr = 0.f, bhz = 0.f, bhn = 0.f;
    if (tid < 256) {
        const int en = tid >> 6;
        bhr = __ldg(&bhh[n0 + en]);
        bhz = __ldg(&bhh[NN + n0 + en]);
        bhn = __ldg(&bhh[2 * NN + n0 + en]);
    }

    // Prefetch x for t=0 into parity buffer 0
    if (tid < 192) {
        const int grp = tid >> 6;
        const int bb  = tid & 63;
        const float4 xv = __ldg((const float4*)(
            g_xproj + (size_t)(bb * TT) * G3 + grp * NN + n0));
        xs[0][grp][0][bb] = xv.x; xs[0][grp][1][bb] = xv.y;
        xs[0][grp][2][bb] = xv.z; xs[0][grp][3][bb] = xv.w;
    }

    const float* wr = &ws[nn][kq * 64];
    const float* wz = &ws[4 + nn][kq * 64];
    const float* wn = &ws[8 + nn][kq * 64];
    __syncthreads();

    for (int t = 0; t < TT; t++) {
        const float* __restrict__ hcur = g_ht[t & 1];
        float*       __restrict__ hnxt = g_ht[(t & 1) ^ 1];
        const int par = t & 1;

        // Partial gates over this thread's 64-k chunk, 4 batches (f32x2).
        unsigned long long ar01 = 0ull, ar23 = 0ull;
        unsigned long long az01 = 0ull, az23 = 0ull;
        unsigned long long an01 = 0ull, an23 = 0ull;
        const float* hk = hcur + kq * 64 * BB + b4 * 4;
#pragma unroll 8
        for (int k = 0; k < 64; k++) {
            const ulonglong2 hv = *(const ulonglong2*)(hk + (size_t)k * BB);
            const unsigned long long w0 = dup2(wr[k]);
            const unsigned long long w1 = dup2(wz[k]);
            const unsigned long long w2 = dup2(wn[k]);
            fma2(ar01, hv.x, w0); fma2(ar23, hv.y, w0);
            fma2(az01, hv.x, w1); fma2(az23, hv.y, w1);
            fma2(an01, hv.x, w2); fma2(an23, hv.y, w2);
        }
        {
            float2 a = unpack2(ar01), b = unpack2(ar23);
            *(float4*)&red[kq][0][nn][b4 * 4] = make_float4(a.x, a.y, b.x, b.y);
            a = unpack2(az01); b = unpack2(az23);
            *(float4*)&red[kq][1][nn][b4 * 4] = make_float4(a.x, a.y, b.x, b.y);
            a = unpack2(an01); b = unpack2(an23);
            *(float4*)&red[kq][2][nn][b4 * 4] = make_float4(a.x, a.y, b.x, b.y);
        }
        __syncthreads();

        // Epilogue: 256 threads, 1 batch each for one n-column
        if (tid < 256) {
            const int en = tid >> 6;    // n-col 0..3
            const int eb = tid & 63;    // batch
            float sr = 0.f, sz = 0.f, sq = 0.f;
#pragma unroll
            for (int q = 0; q < 8; q++) {
                sr += red[q][0][en][eb];
                sz += red[q][1][en][eb];
                sq += red[q][2][en][eb];
            }
            const float hp = hcur[(n0 + en) * BB + eb];
            const float xr = xs[par][0][en][eb];
            const float xz = xs[par][1][en][eb];
            const float xn = xs[par][2][en][eb];

            const float r  = 1.0f / (1.0f + __expf(-(xr + sr + bhr)));
            const float z  = 1.0f / (1.0f + __expf(-(xz + sz + bhz)));
            const float nv = tanhf(xn + r * (sq + bhn));
            const float hn = (1.0f - z) * nv + z * hp;

            __stcg(&hnxt[(n0 + en) * BB + eb], hn);  // coalesced, L2-direct
            hs[en][eb] = hn;
        }
        __syncthreads();   // hnxt + hs complete; safe to arrive at barrier

        // These OVERLAP the barrier wait below (independent of other CTAs):
        //   out-writeback (never re-read) + x prefetch for t+1.
        if (tid < 64) {
            const int b = tid;
            __stcg((float4*)(out + (size_t)(b * TT + t) * NN + n0),
                   make_float4(hs[0][b], hs[1][b], hs[2][b], hs[3][b]));
        } else if (tid >= 256 && tid < 448 && t + 1 < TT) {
            const int grp = (tid - 256) >> 6;
            const int bb  = tid & 63;
            const float4 xv = __ldg((const float4*)(
                g_xproj + (size_t)(bb * TT + t + 1) * G3 + grp * NN + n0));
            float* xd = &xs[par ^ 1][grp][0][bb];
            xd[0] = xv.x; xd[64] = xv.y; xd[128] = xv.z; xd[192] = xv.w;
        }

        // Grid barrier: acq_rel arrival, release-publish, hard-spin acquire
        // poll (no nanosleep: wake latency = one L2 round trip).
        if (t < TT - 1) {
            if (tid == 0) {
                const unsigned target = (unsigned)(t + 1);
                unsigned arrived;
                asm volatile("atom.acq_rel.gpu.global.add.u32 %0, [%1], %2;"
                             : "=r"(arrived) : "l"(&g_count.v), "r"(1u) : "memory");
                if (arrived + 1u == target * (unsigned)GRID_SCAN) {
                    asm volatile("st.release.gpu.global.u32 [%0], %1;"
                                 :: "l"(&g_gen.v), "r"(target) : "memory");
                } else {
                    unsigned g;
                    do {
                        asm volatile("ld.acquire.gpu.global.u32 %0, [%1];"
                                     : "=r"(g) : "l"(&g_gen.v) : "memory");
                    } while (g < target);
                }
            }
            __syncthreads();
            __threadfence();   // acquire: CCTL.IVALL so L1 h lines refresh
        }
    }
}

// ---------------------------------------------------------------------------
// Launch
// ---------------------------------------------------------------------------
extern "C" void kernel_launch(void* const* d_in, const int* in_sizes, int n_in,
                              void* d_out, int out_size) {
    const float* h_enc = (const float*)d_in[0];
    const float* W_ih  = (const float*)d_in[1];
    const float* W_hh  = (const float*)d_in[2];
    const float* b_ih  = (const float*)d_in[3];
    const float* b_hh  = (const float*)d_in[4];
    float* out = (float*)d_out;

    float* xproj_ptr = nullptr;
    cudaGetSymbolAddress((void**)&xproj_ptr, g_xproj);

    dim3 grid(G3 / 128, (BB * TT) / 128);
    xproj_kernel<<<grid, 256>>>(h_enc, W_ih, b_ih, xproj_ptr);
    gru_scan_kernel<<<GRID_SCAN, SCAN_THREADS>>>(W_hh, b_hh, out);
}

// round 11
// speedup vs baseline: 1.0551x; 1.0551x over previous
#include <cuda_runtime.h>
#include <cuda_bf16.h>
#include <math.h>

// Problem constants
#define BB 64
#define TT 1000
#define NN 512
#define G3 1536
#define GRID_SCAN 128
#define N_LEAF 8          // barrier leaves (16 CTAs each)

// ---------------------------------------------------------------------------
// f32x2 packed-FMA helpers (PTX-only; ptxas never auto-fuses)
// ---------------------------------------------------------------------------
__device__ __forceinline__ unsigned long long dup2(float x) {
    unsigned long long r;
    asm("mov.b64 %0, {%1, %1};" : "=l"(r) : "f"(x));
    return r;
}
__device__ __forceinline__ void fma2(unsigned long long& d,
                                     unsigned long long a,
                                     unsigned long long b) {
    asm("fma.rn.f32x2 %0, %1, %2, %0;" : "+l"(d) : "l"(a), "l"(b));
}
__device__ __forceinline__ void add2(unsigned long long& d, unsigned long long a) {
    asm("add.rn.f32x2 %0, %0, %1;" : "+l"(d) : "l"(a));
}
__device__ __forceinline__ float2 unpack2(unsigned long long v) {
    float2 f;
    asm("mov.b64 {%0, %1}, %2;" : "=f"(f.x), "=f"(f.y) : "l"(v));
    return f;
}

// ---------------------------------------------------------------------------
// Scratch. Every barrier word on its own 128B L2 line. Two-level arrival
// tree: 8 leaves x 16 CTAs -> root x 8 -> gen publish. Flat 128-way
// single-line atomics serialized ~4000 cyc/step at the LTS; the tree's
// critical path is ~1100-1400 cyc.
// ---------------------------------------------------------------------------
struct __align__(128) Pad128 { unsigned v; unsigned pad[31]; };
__device__ Pad128   g_leaf[N_LEAF];                 // leaf arrival counters
__device__ Pad128   g_root;                         // root arrival counter
__device__ Pad128   g_gen;                          // generation (read-mostly)
__device__ float    g_xproj[(size_t)BB * TT * G3];  // [B][T][3N]
__device__ float    g_ht[2][NN * BB];               // transposed hidden [k][b]

// ---------------------------------------------------------------------------
// Kernel 1: x_proj = h_enc @ W_ih^T + b_ih. 128x128x16 tiles, 8x8 microtile,
// f32x2-packed j. Block (0,0) also resets barriers + zeroes h0 (every replay).
// ---------------------------------------------------------------------------
__global__ void __launch_bounds__(256) xproj_kernel(
    const float* __restrict__ A,     // [64000][512]
    const float* __restrict__ Wih,   // [1536][512]
    const float* __restrict__ bih,   // [1536]
    float* __restrict__ C)           // [64000][1536]
{
    __shared__ float As[16][128];
    __shared__ float Bs[16][128];

    const int tid   = threadIdx.x;
    const int mBase = blockIdx.y * 128;
    const int nBase = blockIdx.x * 128;
    const int tx = tid & 15;
    const int ty = tid >> 4;

    if (blockIdx.x == 0 && blockIdx.y == 0) {
        if (tid == 0) {
            for (int l = 0; l < N_LEAF; l++) g_leaf[l].v = 0u;
            g_root.v = 0u;
            g_gen.v  = 0u;
        }
        for (int j = tid; j < NN * BB; j += 256) g_ht[0][j] = 0.0f;
    }

    unsigned long long acc2[8][4];
#pragma unroll
    for (int i = 0; i < 8; i++)
#pragma unroll
        for (int j = 0; j < 4; j++) acc2[i][j] = 0ull;

    const int lr = tid >> 2;
    const int lk = (tid & 3) << 2;
    const float* Aptr = A   + (size_t)(mBase + lr) * NN + lk;
    const float* Bptr = Wih + (size_t)(nBase + lr) * NN + lk;

    for (int kt = 0; kt < NN; kt += 16) {
        const float4 a0 = *(const float4*)(Aptr + kt);
        const float4 a1 = *(const float4*)(Aptr + 64 * NN + kt);
        const float4 b0 = *(const float4*)(Bptr + kt);
        const float4 b1 = *(const float4*)(Bptr + 64 * NN + kt);
        __syncthreads();
        As[lk + 0][lr] = a0.x; As[lk + 1][lr] = a0.y; As[lk + 2][lr] = a0.z; As[lk + 3][lr] = a0.w;
        As[lk + 0][64 + lr] = a1.x; As[lk + 1][64 + lr] = a1.y; As[lk + 2][64 + lr] = a1.z; As[lk + 3][64 + lr] = a1.w;
        Bs[lk + 0][lr] = b0.x; Bs[lk + 1][lr] = b0.y; Bs[lk + 2][lr] = b0.z; Bs[lk + 3][lr] = b0.w;
        Bs[lk + 0][64 + lr] = b1.x; Bs[lk + 1][64 + lr] = b1.y; Bs[lk + 2][64 + lr] = b1.z; Bs[lk + 3][64 + lr] = b1.w;
        __syncthreads();
#pragma unroll
        for (int k = 0; k < 16; k++) {
            float af[8];
            *(float4*)&af[0] = *(const float4*)&As[k][ty * 4];
            *(float4*)&af[4] = *(const float4*)&As[k][64 + ty * 4];
            unsigned long long b2[4];
            *(uint4*)&b2[0] = *(const uint4*)&Bs[k][tx * 4];
            *(uint4*)&b2[2] = *(const uint4*)&Bs[k][64 + tx * 4];
#pragma unroll
            for (int i = 0; i < 8; i++) {
                const unsigned long long ad = dup2(af[i]);
#pragma unroll
                for (int j = 0; j < 4; j++) fma2(acc2[i][j], ad, b2[j]);
            }
        }
    }

    float bias[8];
#pragma unroll
    for (int j = 0; j < 8; j++) {
        int col = nBase + ((j < 4) ? (tx * 4 + j) : (64 + tx * 4 + (j - 4)));
        bias[j] = __ldg(&bih[col]);
    }
#pragma unroll
    for (int i = 0; i < 8; i++) {
        float a[8];
#pragma unroll
        for (int j = 0; j < 4; j++) {
            const float2 v = unpack2(acc2[i][j]);
            a[2 * j] = v.x; a[2 * j + 1] = v.y;
        }
        int row = mBase + ((i < 4) ? (ty * 4 + i) : (64 + ty * 4 + (i - 4)));
        float* cp = C + (size_t)row * G3 + nBase;
        *(float4*)(cp + tx * 4) =
            make_float4(a[0] + bias[0], a[1] + bias[1], a[2] + bias[2], a[3] + bias[3]);
        *(float4*)(cp + 64 + tx * 4) =
            make_float4(a[4] + bias[4], a[5] + bias[5], a[6] + bias[6], a[7] + bias[7]);
    }
}

// ---------------------------------------------------------------------------
// Kernel 2: persistent cooperative GRU scan (best-measured R6/R8 base).
//   128 CTAs x 256 threads. thread=(kq 0..3, nn 0..3, b4 0..15).
//   h READS: plain L1-cached (4x nn-broadcast reuse); one acquire fence/step.
//   h WRITES: __stcg; release via acq_rel arrival chain.
//   Barrier-wait window hides: out-writeback + x_t(t+1) prefetch.
// ---------------------------------------------------------------------------
__global__ void __launch_bounds__(256) gru_scan_kernel(
    const float* __restrict__ Whh,   // [1536][512]
    const float* __restrict__ bhh,   // [1536]
    float* __restrict__ out)         // [B][T][N]
{
    __shared__ unsigned long long wsd[12][514];       // dup'd W: [gate*4+jn][k]
    __shared__ float xs[2][3][4][64];                 // x double buf: [par][gate][nn][b]
    __shared__ unsigned long long red[4][3][4][32];   // [kq][gate][nn][bpair]
    __shared__ float hs[4][64];                       // h_new: [nn][b]

    const int tid = threadIdx.x;
    const int n0  = blockIdx.x * 4;
    const int kq  = tid >> 6;
    const int nn  = (tid >> 4) & 3;
    const int b4  = tid & 15;

    // Load + duplicate W_hh slice once
    for (int i = tid; i < 12 * 512; i += 256) {
        const int row = i >> 9;            // gate*4 + jn
        const int k   = i & 511;
        const int gate = row >> 2;
        const int jn   = row & 3;
        wsd[row][k] = dup2(__ldg(&Whh[(size_t)(gate * NN + n0 + jn) * NN + k]));
    }

    // Epilogue biases (tid<128: en = tid>>5)
    float bhr = 0.f, bhz = 0.f, bhn = 0.f;
    if (tid < 128) {
        const int en = tid >> 5;
        bhr = __ldg(&bhh[n0 + en]);
        bhz = __ldg(&bhh[NN + n0 + en]);
        bhn = __ldg(&bhh[2 * NN + n0 + en]);
    }

    // Prefetch x for t=0 into parity buffer 0
    if (tid < 192) {
        const int grp = tid >> 6;
        const int bb  = tid & 63;
        const float4 xv = __ldg((const float4*)(
            g_xproj + (size_t)(bb * TT) * G3 + grp * NN + n0));
        xs[0][grp][0][bb] = xv.x; xs[0][grp][1][bb] = xv.y;
        xs[0][grp][2][bb] = xv.z; xs[0][grp][3][bb] = xv.w;
    }

    const unsigned long long* wr = &wsd[nn][kq * 128];
    const unsigned long long* wz = &wsd[4 + nn][kq * 128];
    const unsigned long long* wn = &wsd[8 + nn][kq * 128];
    __syncthreads();

    for (int t = 0; t < TT; t++) {
        const float* __restrict__ hcur = g_ht[t & 1];
        float*       __restrict__ hnxt = g_ht[(t & 1) ^ 1];
        const int par = t & 1;

        // Partial gates over this thread's 128-k chunk, 4 batches (f32x2).
        // Plain (L1-cached) h loads: 4x reuse across nn-subgroups.
        unsigned long long ar01 = 0ull, ar23 = 0ull;
        unsigned long long az01 = 0ull, az23 = 0ull;
        unsigned long long an01 = 0ull, an23 = 0ull;
        const float* hk = hcur + kq * 128 * BB + b4 * 4;
#pragma unroll 8
        for (int k = 0; k < 128; k++) {
            const ulonglong2 hv = *(const ulonglong2*)(hk + (size_t)k * BB);
            const unsigned long long w0 = wr[k];
            const unsigned long long w1 = wz[k];
            const unsigned long long w2 = wn[k];
            fma2(ar01, hv.x, w0); fma2(ar23, hv.y, w0);
            fma2(az01, hv.x, w1); fma2(az23, hv.y, w1);
            fma2(an01, hv.x, w2); fma2(an23, hv.y, w2);
        }
        *(ulonglong2*)&red[kq][0][nn][2 * b4] = make_ulonglong2(ar01, ar23);
        *(ulonglong2*)&red[kq][1][nn][2 * b4] = make_ulonglong2(az01, az23);
        *(ulonglong2*)&red[kq][2][nn][2 * b4] = make_ulonglong2(an01, an23);
        __syncthreads();

        // Epilogue: 128 threads, 2 batches each; writes transposed h directly
        if (tid < 128) {
            const int en = tid >> 5;    // n-col 0..3
            const int eb = tid & 31;    // batch pair
            unsigned long long sr = red[0][0][en][eb];
            unsigned long long sz = red[0][1][en][eb];
            unsigned long long sq = red[0][2][en][eb];
#pragma unroll
            for (int q = 1; q < 4; q++) {
                add2(sr, red[q][0][en][eb]);
                add2(sz, red[q][1][en][eb]);
                add2(sq, red[q][2][en][eb]);
            }
            const float2 arf = unpack2(sr);
            const float2 azf = unpack2(sz);
            const float2 aqf = unpack2(sq);
            const float2 hp = *(const float2*)(hcur + (n0 + en) * BB + eb * 2);
            const float2 xr = *(const float2*)&xs[par][0][en][eb * 2];
            const float2 xz = *(const float2*)&xs[par][1][en][eb * 2];
            const float2 xn = *(const float2*)&xs[par][2][en][eb * 2];

            const float r0  = 1.0f / (1.0f + __expf(-(xr.x + arf.x + bhr)));
            const float z0  = 1.0f / (1.0f + __expf(-(xz.x + azf.x + bhz)));
            const float n0v = tanhf(xn.x + r0 * (aqf.x + bhn));
            const float h0  = (1.0f - z0) * n0v + z0 * hp.x;

            const float r1  = 1.0f / (1.0f + __expf(-(xr.y + arf.y + bhr)));
            const float z1  = 1.0f / (1.0f + __expf(-(xz.y + azf.y + bhz)));
            const float n1v = tanhf(xn.y + r1 * (aqf.y + bhn));
            const float h1  = (1.0f - z1) * n1v + z1 * hp.y;

            __stcg((float2*)(hnxt + (n0 + en) * BB + eb * 2), make_float2(h0, h1));
            hs[en][eb * 2 + 0] = h0;
            hs[en][eb * 2 + 1] = h1;
        }
        __syncthreads();   // hnxt + hs complete; safe to arrive at barrier

        // OVERLAPS the barrier wait: out-writeback (never re-read) and
        // x prefetch for t+1 into the other parity buffer.
        if (tid < 64) {
            const int b = tid;
            __stcg((float4*)(out + (size_t)(b * TT + t) * NN + n0),
                   make_float4(hs[0][b], hs[1][b], hs[2][b], hs[3][b]));
        } else if (t + 1 < TT) {   // tid 64..255 -> 192 threads, 3 gates x 64 b
            const int grp = (tid - 64) >> 6;
            const int bb  = tid & 63;
            const float4 xv = __ldg((const float4*)(
                g_xproj + (size_t)(bb * TT + t + 1) * G3 + grp * NN + n0));
            float* xd = &xs[par ^ 1][grp][0][bb];
            xd[0] = xv.x; xd[64] = xv.y; xd[128] = xv.z; xd[192] = xv.w;
        }

        // Two-level grid barrier. Cumulative monotonic counts at leaf+root.
        // acq_rel RMWs chain the release from h-stores to the gen publish.
        if (t < TT - 1) {
            if (tid == 0) {
                const unsigned target = (unsigned)(t + 1);
                const int leaf = blockIdx.x >> 4;      // 16 CTAs per leaf
                unsigned a;
                asm volatile("atom.acq_rel.gpu.global.add.u32 %0, [%1], %2;"
                             : "=r"(a) : "l"(&g_leaf[leaf].v), "r"(1u) : "memory");
                bool published = false;
                if (a + 1u == target * 16u) {          // last in leaf
                    unsigned r;
                    asm volatile("atom.acq_rel.gpu.global.add.u32 %0, [%1], %2;"
                                 : "=r"(r) : "l"(&g_root.v), "r"(1u) : "memory");
                    if (r + 1u == target * (unsigned)N_LEAF) {  // last leaf
                        asm volatile("st.release.gpu.global.u32 [%0], %1;"
                                     :: "l"(&g_gen.v), "r"(target) : "memory");
                        published = true;
                    }
                }
                if (!published) {
                    unsigned g;
                    while (true) {
                        asm volatile("ld.acquire.gpu.global.u32 %0, [%1];"
                                     : "=r"(g) : "l"(&g_gen.v) : "memory");
                        if (g >= target) break;
                        __nanosleep(32);
                    }
                }
            }
            __syncthreads();
            __threadfence();   // acquire: CCTL.IVALL so L1 h lines refresh
        }
    }
}

// ---------------------------------------------------------------------------
// Launch
// ---------------------------------------------------------------------------
extern "C" void kernel_launch(void* const* d_in, const int* in_sizes, int n_in,
                              void* d_out, int out_size) {
    const float* h_enc = (const float*)d_in[0];
    const float* W_ih  = (const float*)d_in[1];
    const float* W_hh  = (const float*)d_in[2];
    const float* b_ih  = (const float*)d_in[3];
    const float* b_hh  = (const float*)d_in[4];
    float* out = (float*)d_out;

    float* xproj_ptr = nullptr;
    cudaGetSymbolAddress((void**)&xproj_ptr, g_xproj);

    dim3 grid(G3 / 128, (BB * TT) / 128);
    xproj_kernel<<<grid, 256>>>(h_enc, W_ih, b_ih, xproj_ptr);
    gru_scan_kernel<<<GRID_SCAN, 256>>>(W_hh, b_hh, out);
}

// round 12
// speedup vs baseline: 1.2730x; 1.2065x over previous
#include <cuda_runtime.h>
#include <cuda_bf16.h>
#include <math.h>

// Problem constants
#define BB 64
#define TT 1000
#define NN 512
#define G3 1536
#define GRID_SCAN 128     // 2 groups x 64 CTAs
#define GROUP_CTAS 64
#define GB 32             // batches per group

// ---------------------------------------------------------------------------
// f32x2 packed-FMA helpers (PTX-only; ptxas never auto-fuses)
// ---------------------------------------------------------------------------
__device__ __forceinline__ unsigned long long dup2(float x) {
    unsigned long long r;
    asm("mov.b64 %0, {%1, %1};" : "=l"(r) : "f"(x));
    return r;
}
__device__ __forceinline__ void fma2(unsigned long long& d,
                                     unsigned long long a,
                                     unsigned long long b) {
    asm("fma.rn.f32x2 %0, %1, %2, %0;" : "+l"(d) : "l"(a), "l"(b));
}
__device__ __forceinline__ float2 unpack2(unsigned long long v) {
    float2 f;
    asm("mov.b64 {%0, %1}, %2;" : "=f"(f.x), "=f"(f.y) : "l"(v));
    return f;
}

// ---------------------------------------------------------------------------
// Scratch. Per-group barrier words, each on its own 128B L2 line.
// ---------------------------------------------------------------------------
struct __align__(128) Pad128 { unsigned v; unsigned pad[31]; };
__device__ Pad128   g_cnt[2];                       // per-group arrival counters
__device__ Pad128   g_gen[2];                       // per-group generation flags
__device__ float    g_xproj[(size_t)BB * TT * G3];  // [B][T][3N]
__device__ float    g_ht[2][NN * BB];               // transposed hidden [k][b]

// ---------------------------------------------------------------------------
// Kernel 1: x_proj = h_enc @ W_ih^T + b_ih. 128x128x16 tiles, 8x8 microtile,
// f32x2-packed j. Block (0,0) also resets barriers + zeroes h0 (every replay).
// ---------------------------------------------------------------------------
__global__ void __launch_bounds__(256) xproj_kernel(
    const float* __restrict__ A,     // [64000][512]
    const float* __restrict__ Wih,   // [1536][512]
    const float* __restrict__ bih,   // [1536]
    float* __restrict__ C)           // [64000][1536]
{
    __shared__ float As[16][128];
    __shared__ float Bs[16][128];

    const int tid   = threadIdx.x;
    const int mBase = blockIdx.y * 128;
    const int nBase = blockIdx.x * 128;
    const int tx = tid & 15;
    const int ty = tid >> 4;

    if (blockIdx.x == 0 && blockIdx.y == 0) {
        if (tid == 0) {
            g_cnt[0].v = 0u; g_cnt[1].v = 0u;
            g_gen[0].v = 0u; g_gen[1].v = 0u;
        }
        for (int j = tid; j < NN * BB; j += 256) g_ht[0][j] = 0.0f;
    }

    unsigned long long acc2[8][4];
#pragma unroll
    for (int i = 0; i < 8; i++)
#pragma unroll
        for (int j = 0; j < 4; j++) acc2[i][j] = 0ull;

    const int lr = tid >> 2;
    const int lk = (tid & 3) << 2;
    const float* Aptr = A   + (size_t)(mBase + lr) * NN + lk;
    const float* Bptr = Wih + (size_t)(nBase + lr) * NN + lk;

    for (int kt = 0; kt < NN; kt += 16) {
        const float4 a0 = *(const float4*)(Aptr + kt);
        const float4 a1 = *(const float4*)(Aptr + 64 * NN + kt);
        const float4 b0 = *(const float4*)(Bptr + kt);
        const float4 b1 = *(const float4*)(Bptr + 64 * NN + kt);
        __syncthreads();
        As[lk + 0][lr] = a0.x; As[lk + 1][lr] = a0.y; As[lk + 2][lr] = a0.z; As[lk + 3][lr] = a0.w;
        As[lk + 0][64 + lr] = a1.x; As[lk + 1][64 + lr] = a1.y; As[lk + 2][64 + lr] = a1.z; As[lk + 3][64 + lr] = a1.w;
        Bs[lk + 0][lr] = b0.x; Bs[lk + 1][lr] = b0.y; Bs[lk + 2][lr] = b0.z; Bs[lk + 3][lr] = b0.w;
        Bs[lk + 0][64 + lr] = b1.x; Bs[lk + 1][64 + lr] = b1.y; Bs[lk + 2][64 + lr] = b1.z; Bs[lk + 3][64 + lr] = b1.w;
        __syncthreads();
#pragma unroll
        for (int k = 0; k < 16; k++) {
            float af[8];
            *(float4*)&af[0] = *(const float4*)&As[k][ty * 4];
            *(float4*)&af[4] = *(const float4*)&As[k][64 + ty * 4];
            unsigned long long b2[4];
            *(uint4*)&b2[0] = *(const uint4*)&Bs[k][tx * 4];
            *(uint4*)&b2[2] = *(const uint4*)&Bs[k][64 + tx * 4];
#pragma unroll
            for (int i = 0; i < 8; i++) {
                const unsigned long long ad = dup2(af[i]);
#pragma unroll
                for (int j = 0; j < 4; j++) fma2(acc2[i][j], ad, b2[j]);
            }
        }
    }

    float bias[8];
#pragma unroll
    for (int j = 0; j < 8; j++) {
        int col = nBase + ((j < 4) ? (tx * 4 + j) : (64 + tx * 4 + (j - 4)));
        bias[j] = __ldg(&bih[col]);
    }
#pragma unroll
    for (int i = 0; i < 8; i++) {
        float a[8];
#pragma unroll
        for (int j = 0; j < 4; j++) {
            const float2 v = unpack2(acc2[i][j]);
            a[2 * j] = v.x; a[2 * j + 1] = v.y;
        }
        int row = mBase + ((i < 4) ? (ty * 4 + i) : (64 + ty * 4 + (i - 4)));
        float* cp = C + (size_t)row * G3 + nBase;
        *(float4*)(cp + tx * 4) =
            make_float4(a[0] + bias[0], a[1] + bias[1], a[2] + bias[2], a[3] + bias[3]);
        *(float4*)(cp + 64 + tx * 4) =
            make_float4(a[4] + bias[4], a[5] + bias[5], a[6] + bias[6], a[7] + bias[7]);
    }
}

// ---------------------------------------------------------------------------
// Kernel 2: persistent GRU scan, TWO independent batch-group scans.
//   group g = blockIdx.x>>6 owns batches [32g,32g+32) with its own 64-CTA
//   barrier. CTA covers 8 n-cols x 32 batches. thread=(kq 0..3, nn 0..7,
//   b8 0..7): 128-k chunk, one n-col, 4 batches, f32x2 -> 6 FFMA2/k (same
//   proven mainloop as R6). h via L1 (8-warp line reuse); h-refill per CTA
//   halves to 64KB; arrival domain halves to 64.
// ---------------------------------------------------------------------------
__global__ void __launch_bounds__(256) gru_scan_kernel(
    const float* __restrict__ Whh,   // [1536][512]
    const float* __restrict__ bhh,   // [1536]
    float* __restrict__ out)         // [B][T][N]
{
    __shared__ float ws[24][520];        // W slice: [gate*8+jn][k]  (~49.9KB)
    __shared__ float xs[3][8][32];       // x_t: [gate][nn][b]
    __shared__ float red[4][3][8][32];   // partials: [kq][gate][nn][b] (12KB)
    __shared__ float hs[8][32];          // h_new: [nn][b]

    const int tid   = threadIdx.x;
    const int grp   = blockIdx.x >> 6;        // batch group 0/1
    const int cid   = blockIdx.x & 63;        // CTA within group
    const int nbase = cid * 8;
    const int bbase = grp * GB;
    const int kq  = tid >> 6;                 // 0..3
    const int nn  = (tid >> 3) & 7;           // 0..7
    const int b8  = tid & 7;                  // 4-batch group

    // Load W_hh slice once (un-duplicated; dup2 in-loop rides idle ALU pipe)
    for (int i = tid; i < 24 * 512; i += 256) {
        const int row = i >> 9;               // gate*8 + jn
        const int k   = i & 511;
        const int gate = row >> 3;
        const int jn   = row & 7;
        ws[row][k] = __ldg(&Whh[(size_t)(gate * NN + nbase + jn) * NN + k]);
    }

    // Epilogue biases: all 256 threads, en = tid>>5
    const int en_ = tid >> 5;
    const float bhr = __ldg(&bhh[nbase + en_]);
    const float bhz = __ldg(&bhh[NN + nbase + en_]);
    const float bhn = __ldg(&bhh[2 * NN + nbase + en_]);

    const float* wr = &ws[nn][kq * 128];
    const float* wz = &ws[8 + nn][kq * 128];
    const float* wn = &ws[16 + nn][kq * 128];
    __syncthreads();

    for (int t = 0; t < TT; t++) {
        const float* __restrict__ hcur = g_ht[t & 1];
        float*       __restrict__ hnxt = g_ht[(t & 1) ^ 1];

        // Stage x_proj[:, t, slice] (hidden under the mainloop, R6-proven)
        if (tid < 192) {
            const int gate = tid >> 6;        // 0..2
            const int b    = (tid & 63) >> 1; // 0..31
            const int half = tid & 1;         // 0..1
            const float4 xv = __ldg((const float4*)(
                g_xproj + (size_t)((bbase + b) * TT + t) * G3
                        + gate * NN + nbase + half * 4));
            xs[gate][half * 4 + 0][b] = xv.x;
            xs[gate][half * 4 + 1][b] = xv.y;
            xs[gate][half * 4 + 2][b] = xv.z;
            xs[gate][half * 4 + 3][b] = xv.w;
        }

        // Partial gates over this thread's 128-k chunk, 4 batches (f32x2).
        unsigned long long ar01 = 0ull, ar23 = 0ull;
        unsigned long long az01 = 0ull, az23 = 0ull;
        unsigned long long an01 = 0ull, an23 = 0ull;
        const float* hk = hcur + kq * 128 * BB + bbase + b8 * 4;
#pragma unroll 8
        for (int k = 0; k < 128; k++) {
            const ulonglong2 hv = *(const ulonglong2*)(hk + (size_t)k * BB);
            const unsigned long long w0 = dup2(wr[k]);
            const unsigned long long w1 = dup2(wz[k]);
            const unsigned long long w2 = dup2(wn[k]);
            fma2(ar01, hv.x, w0); fma2(ar23, hv.y, w0);
            fma2(az01, hv.x, w1); fma2(az23, hv.y, w1);
            fma2(an01, hv.x, w2); fma2(an23, hv.y, w2);
        }
        {
            float2 a = unpack2(ar01), b = unpack2(ar23);
            *(float4*)&red[kq][0][nn][b8 * 4] = make_float4(a.x, a.y, b.x, b.y);
            a = unpack2(az01); b = unpack2(az23);
            *(float4*)&red[kq][1][nn][b8 * 4] = make_float4(a.x, a.y, b.x, b.y);
            a = unpack2(an01); b = unpack2(an23);
            *(float4*)&red[kq][2][nn][b8 * 4] = make_float4(a.x, a.y, b.x, b.y);
        }
        __syncthreads();

        // Epilogue: 256 threads, one (n-col, batch) output each
        {
            const int en = tid >> 5;      // 0..7
            const int eb = tid & 31;      // 0..31
            float sr = 0.f, sz = 0.f, sq = 0.f;
#pragma unroll
            for (int q = 0; q < 4; q++) {
                sr += red[q][0][en][eb];
                sz += red[q][1][en][eb];
                sq += red[q][2][en][eb];
            }
            const float hp = hcur[(nbase + en) * BB + bbase + eb];
            const float xr = xs[0][en][eb];
            const float xz = xs[1][en][eb];
            const float xn = xs[2][en][eb];

            const float r  = 1.0f / (1.0f + __expf(-(xr + sr + bhr)));
            const float z  = 1.0f / (1.0f + __expf(-(xz + sz + bhz)));
            const float nv = tanhf(xn + r * (sq + bhn));
            const float hn = (1.0f - z) * nv + z * hp;

            __stcg(&hnxt[(nbase + en) * BB + bbase + eb], hn);  // coalesced
            hs[en][eb] = hn;
        }
        __syncthreads();   // hnxt + hs complete; safe to arrive at barrier

        // Out-writeback overlaps the barrier wait (out is never re-read).
        if (tid < 128) {
            const int b  = tid >> 2;      // 0..31
            const int nq = tid & 3;       // 0..3 -> n pair
            __stcg((float2*)(out + (size_t)((bbase + b) * TT + t) * NN
                             + nbase + nq * 2),
                   make_float2(hs[nq * 2][b], hs[nq * 2 + 1][b]));
        }

        // Per-group flat barrier (64 arrivals): acq_rel arrival orders the
        // stcg h-stores; release-publish g_gen[grp]; acquire-poll + one
        // acquire fence (CCTL.IVALL) to refresh L1 h lines.
        if (t < TT - 1) {
            if (tid == 0) {
                const unsigned target = (unsigned)(t + 1);
                unsigned arrived;
                asm volatile("atom.acq_rel.gpu.global.add.u32 %0, [%1], %2;"
                             : "=r"(arrived) : "l"(&g_cnt[grp].v), "r"(1u) : "memory");
                if (arrived + 1u == target * (unsigned)GROUP_CTAS) {
                    asm volatile("st.release.gpu.global.u32 [%0], %1;"
                                 :: "l"(&g_gen[grp].v), "r"(target) : "memory");
                } else {
                    unsigned g;
                    while (true) {
                        asm volatile("ld.acquire.gpu.global.u32 %0, [%1];"
                                     : "=r"(g) : "l"(&g_gen[grp].v) : "memory");
                        if (g >= target) break;
                        __nanosleep(32);
                    }
                }
            }
            __syncthreads();
            __threadfence();   // acquire: CCTL.IVALL so L1 h lines refresh
        }
    }
}

// ---------------------------------------------------------------------------
// Launch
// ---------------------------------------------------------------------------
extern "C" void kernel_launch(void* const* d_in, const int* in_sizes, int n_in,
                              void* d_out, int out_size) {
    const float* h_enc = (const float*)d_in[0];
    const float* W_ih  = (const float*)d_in[1];
    const float* W_hh  = (const float*)d_in[2];
    const float* b_ih  = (const float*)d_in[3];
    const float* b_hh  = (const float*)d_in[4];
    float* out = (float*)d_out;

    float* xproj_ptr = nullptr;
    cudaGetSymbolAddress((void**)&xproj_ptr, g_xproj);

    dim3 grid(G3 / 128, (BB * TT) / 128);
    xproj_kernel<<<grid, 256>>>(h_enc, W_ih, b_ih, xproj_ptr);
    gru_scan_kernel<<<GRID_SCAN, 256>>>(W_hh, b_hh, out);
}

// round 14
// speedup vs baseline: 1.2947x; 1.0170x over previous
#include <cuda_runtime.h>
#include <cuda_bf16.h>
#include <math.h>

// Problem constants
#define BB 64
#define TT 1000
#define NN 512
#define G3 1536
#define SCAN_CTAS 64          // scan: 64 CTAs x 8 n-cols
#define WORK_CTAS 84          // xproj workers
#define TOTAL_CTAS (SCAN_CTAS + WORK_CTAS)   // 148 = #SMs
#define YT 500                // xproj y-tiles (each covers 2 t-slices x 64 b)
#define XT 12                 // xproj x-tiles (1536/128)

typedef unsigned long long ull;

// ---------------------------------------------------------------------------
// f32x2 packed-FMA helpers (PTX-only; ptxas never auto-fuses)
// ---------------------------------------------------------------------------
__device__ __forceinline__ ull dup2(float x) {
    ull r; asm("mov.b64 %0, {%1, %1};" : "=l"(r) : "f"(x)); return r;
}
__device__ __forceinline__ void fma2(ull& d, ull a, ull b) {
    asm("fma.rn.f32x2 %0, %1, %2, %0;" : "+l"(d) : "l"(a), "l"(b));
}
__device__ __forceinline__ void add2(ull& d, ull a) {
    asm("add.rn.f32x2 %0, %0, %1;" : "+l"(d) : "l"(a));
}
__device__ __forceinline__ float2 unpack2(ull v) {
    float2 f; asm("mov.b64 {%0, %1}, %2;" : "=f"(f.x), "=f"(f.y) : "l"(v));
    return f;
}

// ---------------------------------------------------------------------------
// Scratch. Every sync word on its own 128B L2 line.
// ---------------------------------------------------------------------------
struct __align__(128) Pad128 { unsigned v; unsigned pad[31]; };
__device__ Pad128   g_cnt;                          // scan barrier arrivals
__device__ Pad128   g_gen;                          // scan barrier generation
__device__ Pad128   g_xdone[YT];                    // per-y-tile completion (==12)
__device__ float    g_xproj[(size_t)BB * TT * G3];  // TRANSPOSED: [t*64+b][3N]
__device__ float    g_ht[2][NN * BB];               // transposed hidden [k][b]

// SMEM pool offsets (bytes)
#define OFF_WSD 0                     // ull [3][4][512][2]  = 98304
#define OFF_XS  98304                 // float [3][8][64]    = 6144
#define OFF_RED 104448                // ull [4][3][8][32]   = 24576
#define OFF_HS  129024                // float [8][64]       = 2048
#define SMEM_POOL 131200

// ---------------------------------------------------------------------------
// Init: reset all flags + zero h0 (must run every graph replay)
// ---------------------------------------------------------------------------
__global__ void init_kernel() {
    const int i = blockIdx.x * blockDim.x + threadIdx.x;
    if (i == 0) { g_cnt.v = 0u; g_gen.v = 0u; }
    for (int j = i; j < YT; j += gridDim.x * blockDim.x) g_xdone[j].v = 0u;
    for (int j = i; j < NN * BB; j += gridDim.x * blockDim.x) g_ht[0][j] = 0.0f;
}

// ---------------------------------------------------------------------------
// Worker role: stream xproj tiles (128x128x512, 8x8 microtile, f32x2).
// m = t*64 + b  (y-tile y covers t in {2y, 2y+1}, all 64 batches).
// Publish protocol: ALL threads __threadfence() (stores -> gpu-visible),
// __syncthreads(), then tid0 release-add on g_xdone[y].
// ---------------------------------------------------------------------------
__device__ void xproj_worker(char* pool, int w,
                             const float* __restrict__ A,
                             const float* __restrict__ Wih,
                             const float* __restrict__ bih,
                             float* __restrict__ C) {
    float (*As)[128] = (float(*)[128])pool;            // [16][128] 8KB
    float (*Bs)[128] = (float(*)[128])(pool + 8192);   // [16][128] 8KB

    const int tid = threadIdx.x;
    const int tx = tid & 15;
    const int ty = tid >> 4;
    const int lr = tid >> 2;           // 0..63
    const int lk = (tid & 3) << 2;     // 0,4,8,12

    for (int idx = w; idx < YT * XT; idx += WORK_CTAS) {
        const int y = idx / XT;
        const int x = idx - y * XT;
        const int mBase = y * 128;
        const int nBase = x * 128;

        // Row m -> (b = m&63, t = m>>6); rows m and m+64: same b, t+1
        const int m0 = mBase + lr;
        const int b0 = m0 & 63;
        const int t0 = m0 >> 6;
        const float* Aptr = A + (size_t)(b0 * TT + t0) * NN + lk;
        const float* Bptr = Wih + (size_t)(nBase + lr) * NN + lk;

        ull acc2[8][4];
#pragma unroll
        for (int i = 0; i < 8; i++)
#pragma unroll
            for (int j = 0; j < 4; j++) acc2[i][j] = 0ull;

        for (int kt = 0; kt < NN; kt += 16) {
            const float4 a0 = *(const float4*)(Aptr + kt);
            const float4 a1 = *(const float4*)(Aptr + NN + kt);   // t0+1 row
            const float4 b0v = *(const float4*)(Bptr + kt);
            const float4 b1v = *(const float4*)(Bptr + 64 * NN + kt);
            __syncthreads();
            As[lk + 0][lr] = a0.x; As[lk + 1][lr] = a0.y; As[lk + 2][lr] = a0.z; As[lk + 3][lr] = a0.w;
            As[lk + 0][64 + lr] = a1.x; As[lk + 1][64 + lr] = a1.y; As[lk + 2][64 + lr] = a1.z; As[lk + 3][64 + lr] = a1.w;
            Bs[lk + 0][lr] = b0v.x; Bs[lk + 1][lr] = b0v.y; Bs[lk + 2][lr] = b0v.z; Bs[lk + 3][lr] = b0v.w;
            Bs[lk + 0][64 + lr] = b1v.x; Bs[lk + 1][64 + lr] = b1v.y; Bs[lk + 2][64 + lr] = b1v.z; Bs[lk + 3][64 + lr] = b1v.w;
            __syncthreads();
#pragma unroll
            for (int k = 0; k < 16; k++) {
                float af[8];
                *(float4*)&af[0] = *(const float4*)&As[k][ty * 4];
                *(float4*)&af[4] = *(const float4*)&As[k][64 + ty * 4];
                ull b2[4];
                *(uint4*)&b2[0] = *(const uint4*)&Bs[k][tx * 4];
                *(uint4*)&b2[2] = *(const uint4*)&Bs[k][64 + tx * 4];
#pragma unroll
                for (int i = 0; i < 8; i++) {
                    const ull ad = dup2(af[i]);
#pragma unroll
                    for (int j = 0; j < 4; j++) fma2(acc2[i][j], ad, b2[j]);
                }
            }
        }

        float bias[8];
#pragma unroll
        for (int j = 0; j < 8; j++) {
            int col = nBase + ((j < 4) ? (tx * 4 + j) : (64 + tx * 4 + (j - 4)));
            bias[j] = __ldg(&bih[col]);
        }
#pragma unroll
        for (int i = 0; i < 8; i++) {
            float a[8];
#pragma unroll
            for (int j = 0; j < 4; j++) {
                const float2 v = unpack2(acc2[i][j]);
                a[2 * j] = v.x; a[2 * j + 1] = v.y;
            }
            int row = mBase + ((i < 4) ? (ty * 4 + i) : (64 + ty * 4 + (i - 4)));
            float* cp = C + (size_t)row * G3 + nBase;
            *(float4*)(cp + tx * 4) =
                make_float4(a[0] + bias[0], a[1] + bias[1], a[2] + bias[2], a[3] + bias[3]);
            *(float4*)(cp + 64 + tx * 4) =
                make_float4(a[4] + bias[4], a[5] + bias[5], a[6] + bias[6], a[7] + bias[7]);
        }

        __threadfence();   // EACH thread: C stores -> gpu-scope visible
        __syncthreads();   // all threads fenced before publish
        if (tid == 0) {
            unsigned dummy;
            asm volatile("atom.release.gpu.global.add.u32 %0, [%1], %2;"
                         : "=r"(dummy) : "l"(&g_xdone[y].v), "r"(1u) : "memory");
        }
    }
}

// ---------------------------------------------------------------------------
// Scan role: 64 CTAs x 256 threads, CTA owns 8 n-cols x 64 batches.
// thread=(kq 0..3, nn 0..3, b4 0..15): 128-k chunk, cols nn & nn+4, 4 batches.
// W pre-duplicated as adjacent f32x2 col-pairs -> 1 LDG.128 + 3 LDS.128 +
// 12 FFMA2 per k, zero MOVs. h via L1; one IVALL/step. Step t gated on
// g_xdone[t>>1]==12 (acquire by tid0 + bar). x loads are PLAIN (no __ldg:
// data is written by concurrent worker CTAs; RO path would be illegal).
// ---------------------------------------------------------------------------
__device__ void gru_scan(char* pool,
                         const float* __restrict__ Whh,
                         const float* __restrict__ bhh,
                         float* __restrict__ out) {
    ull   (*wsd)[4][512][2] = (ull(*)[4][512][2])(pool + OFF_WSD);  // [3][4][512][2]
    float (*xs)[8][64]      = (float(*)[8][64])(pool + OFF_XS);     // [3][8][64]
    ull   (*red)[3][8][32]  = (ull(*)[3][8][32])(pool + OFF_RED);   // [4][3][8][32]
    float (*hs)[64]         = (float(*)[64])(pool + OFF_HS);        // [8][64]

    const int tid   = threadIdx.x;
    const int cid   = blockIdx.x;         // 0..63
    const int nbase = cid * 8;
    const int kq  = tid >> 6;             // 0..3
    const int nn  = (tid >> 4) & 3;       // 0..3 (col pair: nn, nn+4)
    const int b4  = tid & 15;             // 4-batch group

    // Load + duplicate W_hh slice once: adjacent (col nn, col nn+4) pairs
    for (int i = tid; i < 3 * 4 * 512; i += 256) {
        const int g   = i >> 11;          // gate 0..2
        const int nn2 = (i >> 9) & 3;
        const int k   = i & 511;
        wsd[g][nn2][k][0] = dup2(__ldg(&Whh[(size_t)(g * NN + nbase + nn2) * NN + k]));
        wsd[g][nn2][k][1] = dup2(__ldg(&Whh[(size_t)(g * NN + nbase + nn2 + 4) * NN + k]));
    }

    // Epilogue biases: en = tid>>5 -> col nbase+en
    const int en_ = tid >> 5;
    const float bhr = __ldg(&bhh[nbase + en_]);
    const float bhz = __ldg(&bhh[NN + nbase + en_]);
    const float bhn = __ldg(&bhh[2 * NN + nbase + en_]);

    const ulonglong2* wr = (const ulonglong2*)&wsd[0][nn][kq * 128][0];
    const ulonglong2* wz = (const ulonglong2*)&wsd[1][nn][kq * 128][0];
    const ulonglong2* wn = (const ulonglong2*)&wsd[2][nn][kq * 128][0];
    __syncthreads();

    for (int t = 0; t < TT; t++) {
        const float* __restrict__ hcur = g_ht[t & 1];
        float*       __restrict__ hnxt = g_ht[(t & 1) ^ 1];

        // Gate on xproj progress for this t-slice (usually already set).
        // Acquire by tid0 + bar.sync extends the ordering to the whole CTA.
        if (tid == 0) {
            const int y = t >> 1;
            unsigned d;
            while (true) {
                asm volatile("ld.acquire.gpu.global.u32 %0, [%1];"
                             : "=r"(d) : "l"(&g_xdone[y].v) : "memory");
                if (d >= (unsigned)XT) break;
                __nanosleep(64);
            }
        }
        __syncthreads();

        // Stage x_proj[t, :, slice] — PLAIN loads (writer is a peer CTA)
        if (tid < 192) {
            const int gate = tid >> 6;    // 0..2
            const int b    = tid & 63;
            const float* xb = g_xproj + (size_t)(t * BB + b) * G3
                            + gate * NN + nbase;
            const float4 v0 = *(const float4*)xb;
            const float4 v1 = *(const float4*)(xb + 4);
            xs[gate][0][b] = v0.x; xs[gate][1][b] = v0.y;
            xs[gate][2][b] = v0.z; xs[gate][3][b] = v0.w;
            xs[gate][4][b] = v1.x; xs[gate][5][b] = v1.y;
            xs[gate][6][b] = v1.z; xs[gate][7][b] = v1.w;
        }

        // Mainloop: 128-k chunk, 2 n-cols, 4 batches -> 12 FFMA2/k, no MOVs
        ull a0r01 = 0, a0r23 = 0, a0z01 = 0, a0z23 = 0, a0n01 = 0, a0n23 = 0;
        ull a1r01 = 0, a1r23 = 0, a1z01 = 0, a1z23 = 0, a1n01 = 0, a1n23 = 0;
        const float* hk = hcur + kq * 128 * BB + b4 * 4;
#pragma unroll 8
        for (int k = 0; k < 128; k++) {
            const ulonglong2 hv = *(const ulonglong2*)(hk + (size_t)k * BB);
            const ulonglong2 w0 = wr[k];   // .x = col nn, .y = col nn+4
            const ulonglong2 w1 = wz[k];
            const ulonglong2 w2 = wn[k];
            fma2(a0r01, hv.x, w0.x); fma2(a0r23, hv.y, w0.x);
            fma2(a1r01, hv.x, w0.y); fma2(a1r23, hv.y, w0.y);
            fma2(a0z01, hv.x, w1.x); fma2(a0z23, hv.y, w1.x);
            fma2(a1z01, hv.x, w1.y); fma2(a1z23, hv.y, w1.y);
            fma2(a0n01, hv.x, w2.x); fma2(a0n23, hv.y, w2.x);
            fma2(a1n01, hv.x, w2.y); fma2(a1n23, hv.y, w2.y);
        }
        *(ulonglong2*)&red[kq][0][nn][2 * b4]     = make_ulonglong2(a0r01, a0r23);
        *(ulonglong2*)&red[kq][0][nn + 4][2 * b4] = make_ulonglong2(a1r01, a1r23);
        *(ulonglong2*)&red[kq][1][nn][2 * b4]     = make_ulonglong2(a0z01, a0z23);
        *(ulonglong2*)&red[kq][1][nn + 4][2 * b4] = make_ulonglong2(a1z01, a1z23);
        *(ulonglong2*)&red[kq][2][nn][2 * b4]     = make_ulonglong2(a0n01, a0n23);
        *(ulonglong2*)&red[kq][2][nn + 4][2 * b4] = make_ulonglong2(a1n01, a1n23);
        __syncthreads();

        // Epilogue: 256 threads -> (col 0..7, batch-pair 0..31)
        {
            const int en = tid >> 5;      // col
            const int eb = tid & 31;      // batch pair
            ull sr = red[0][0][en][eb];
            ull sz = red[0][1][en][eb];
            ull sq = red[0][2][en][eb];
#pragma unroll
            for (int q = 1; q < 4; q++) {
                add2(sr, red[q][0][en][eb]);
                add2(sz, red[q][1][en][eb]);
                add2(sq, red[q][2][en][eb]);
            }
            const float2 arf = unpack2(sr);
            const float2 azf = unpack2(sz);
            const float2 aqf = unpack2(sq);
            const float2 hp = *(const float2*)(hcur + (nbase + en) * BB + eb * 2);
            const float2 xr = *(const float2*)&xs[0][en][eb * 2];
            const float2 xz = *(const float2*)&xs[1][en][eb * 2];
            const float2 xn = *(const float2*)&xs[2][en][eb * 2];

            const float r0  = 1.0f / (1.0f + __expf(-(xr.x + arf.x + bhr)));
            const float z0  = 1.0f / (1.0f + __expf(-(xz.x + azf.x + bhz)));
            const float n0v = tanhf(xn.x + r0 * (aqf.x + bhn));
            const float h0  = (1.0f - z0) * n0v + z0 * hp.x;

            const float r1  = 1.0f / (1.0f + __expf(-(xr.y + arf.y + bhr)));
            const float z1  = 1.0f / (1.0f + __expf(-(xz.y + azf.y + bhz)));
            const float n1v = tanhf(xn.y + r1 * (aqf.y + bhn));
            const float h1  = (1.0f - z1) * n1v + z1 * hp.y;

            __stcg((float2*)(hnxt + (nbase + en) * BB + eb * 2),
                   make_float2(h0, h1));
            hs[en][eb * 2 + 0] = h0;
            hs[en][eb * 2 + 1] = h1;
        }
        __threadfence();   // h stores gpu-visible before barrier arrival
        __syncthreads();

        // Out-writeback overlaps the barrier wait (out is never re-read).
        {
            const int b = tid >> 2;       // 0..63
            const int q = tid & 3;        // n pair 0..3
            __stcg((float2*)(out + (size_t)(b * TT + t) * NN + nbase + q * 2),
                   make_float2(hs[q * 2][b], hs[q * 2 + 1][b]));
        }

        // 64-CTA flat barrier: acq_rel arrival; release-publish; acquire-poll;
        // one acquire fence refreshes L1 h lines.
        if (t < TT - 1) {
            if (tid == 0) {
                const unsigned target = (unsigned)(t + 1);
                unsigned arrived;
                asm volatile("atom.acq_rel.gpu.global.add.u32 %0, [%1], %2;"
                             : "=r"(arrived) : "l"(&g_cnt.v), "r"(1u) : "memory");
                if (arrived + 1u == target * (unsigned)SCAN_CTAS) {
                    asm volatile("st.release.gpu.global.u32 [%0], %1;"
                                 :: "l"(&g_gen.v), "r"(target) : "memory");
                } else {
                    unsigned g;
                    while (true) {
                        asm volatile("ld.acquire.gpu.global.u32 %0, [%1];"
                                     : "=r"(g) : "l"(&g_gen.v) : "memory");
                        if (g >= target) break;
                        __nanosleep(32);
                    }
                }
            }
            __syncthreads();
            __threadfence();   // acquire: CCTL.IVALL so L1 h lines refresh
        }
    }
}

// ---------------------------------------------------------------------------
// Fused kernel: CTAs 0..63 = scan, 64..147 = xproj workers. 148 CTAs, occ 1,
// all co-resident; workers terminate on their own -> no deadlock possible.
// ---------------------------------------------------------------------------
__global__ void __launch_bounds__(256) fused_kernel(
    const float* __restrict__ h_enc,
    const float* __restrict__ Wih,
    const float* __restrict__ Whh,
    const float* __restrict__ bih,
    const float* __restrict__ bhh,
    float* __restrict__ xproj,
    float* __restrict__ out) {
    extern __shared__ char pool[];
    if (blockIdx.x < SCAN_CTAS) {
        gru_scan(pool, Whh, bhh, out);
    } else {
        xproj_worker(pool, blockIdx.x - SCAN_CTAS, h_enc, Wih, bih, xproj);
    }
}

// ---------------------------------------------------------------------------
// Launch
// ---------------------------------------------------------------------------
extern "C" void kernel_launch(void* const* d_in, const int* in_sizes, int n_in,
                              void* d_out, int out_size) {
    const float* h_enc = (const float*)d_in[0];
    const float* W_ih  = (const float*)d_in[1];
    const float* W_hh  = (const float*)d_in[2];
    const float* b_ih  = (const float*)d_in[3];
    const float* b_hh  = (const float*)d_in[4];
    float* out = (float*)d_out;

    float* xproj_ptr = nullptr;
    cudaGetSymbolAddress((void**)&xproj_ptr, g_xproj);

    cudaFuncSetAttribute(fused_kernel,
                         cudaFuncAttributeMaxDynamicSharedMemorySize, SMEM_POOL);

    init_kernel<<<64, 256>>>();
    fused_kernel<<<TOTAL_CTAS, 256, SMEM_POOL>>>(
        h_enc, W_ih, W_hh, b_ih, b_hh, xproj_ptr, out);
}

// round 15
// speedup vs baseline: 1.5580x; 1.2034x over previous
#include <cuda_runtime.h>
#include <cuda_bf16.h>
#include <math.h>

// Problem constants
#define BB 64
#define TT 1000
#define NN 512
#define G3 1536
#define SCAN_CTAS 128         // scan: 128 CTAs x 4 n-cols (R6 proven shape)
#define WORK_CTAS 128         // xproj workers (co-resident, 2 CTAs/SM)
#define TOTAL_CTAS (SCAN_CTAS + WORK_CTAS)
#define YT 500                // xproj y-tiles (each covers 2 t-slices x 64 b)
#define XT 12                 // xproj x-tiles (1536/128)

typedef unsigned long long ull;

// ---------------------------------------------------------------------------
// f32x2 packed-FMA helpers (PTX-only; ptxas never auto-fuses)
// ---------------------------------------------------------------------------
__device__ __forceinline__ ull dup2(float x) {
    ull r; asm("mov.b64 %0, {%1, %1};" : "=l"(r) : "f"(x)); return r;
}
__device__ __forceinline__ void fma2(ull& d, ull a, ull b) {
    asm("fma.rn.f32x2 %0, %1, %2, %0;" : "+l"(d) : "l"(a), "l"(b));
}
__device__ __forceinline__ void add2(ull& d, ull a) {
    asm("add.rn.f32x2 %0, %0, %1;" : "+l"(d) : "l"(a));
}
__device__ __forceinline__ float2 unpack2(ull v) {
    float2 f; asm("mov.b64 {%0, %1}, %2;" : "=f"(f.x), "=f"(f.y) : "l"(v));
    return f;
}

// ---------------------------------------------------------------------------
// Scratch. Every sync word on its own 128B L2 line.
// ---------------------------------------------------------------------------
struct __align__(128) Pad128 { unsigned v; unsigned pad[31]; };
__device__ Pad128   g_cnt;                          // scan barrier arrivals
__device__ Pad128   g_gen;                          // scan barrier generation
__device__ Pad128   g_xdone[YT];                    // per-y-tile completion (==12)
__device__ float    g_xproj[(size_t)BB * TT * G3];  // TRANSPOSED: [t*64+b][3N]
__device__ float    g_ht[2][NN * BB];               // transposed hidden [k][b]

// SMEM pool offsets (bytes). Pool sized for the scan role; worker uses 16KB.
#define OFF_WSD 0                     // ull [12][514]      = 49344
#define OFF_XS  49344                 // float [3][4][64]   = 3072
#define OFF_RED 52416                 // ull [4][3][4][32]  = 12288
#define OFF_HS  64704                 // float [4][64]      = 1024
#define SMEM_POOL 65728

// ---------------------------------------------------------------------------
// Init: reset all flags + zero h0 (must run every graph replay)
// ---------------------------------------------------------------------------
__global__ void init_kernel() {
    const int i = blockIdx.x * blockDim.x + threadIdx.x;
    if (i == 0) { g_cnt.v = 0u; g_gen.v = 0u; }
    for (int j = i; j < YT; j += gridDim.x * blockDim.x) g_xdone[j].v = 0u;
    for (int j = i; j < NN * BB; j += gridDim.x * blockDim.x) g_ht[0][j] = 0.0f;
}

// ---------------------------------------------------------------------------
// Worker role (R14-verified): stream xproj tiles (128x128x512, 8x8 microtile,
// f32x2). m = t*64 + b (y-tile y covers t in {2y,2y+1}, all 64 batches).
// Publish: ALL threads __threadfence(), __syncthreads(), tid0 release-add.
// ---------------------------------------------------------------------------
__device__ void xproj_worker(char* pool, int w,
                             const float* __restrict__ A,
                             const float* __restrict__ Wih,
                             const float* __restrict__ bih,
                             float* __restrict__ C) {
    float (*As)[128] = (float(*)[128])pool;            // [16][128] 8KB
    float (*Bs)[128] = (float(*)[128])(pool + 8192);   // [16][128] 8KB

    const int tid = threadIdx.x;
    const int tx = tid & 15;
    const int ty = tid >> 4;
    const int lr = tid >> 2;           // 0..63
    const int lk = (tid & 3) << 2;     // 0,4,8,12

    for (int idx = w; idx < YT * XT; idx += WORK_CTAS) {
        const int y = idx / XT;
        const int x = idx - y * XT;
        const int mBase = y * 128;
        const int nBase = x * 128;

        const int m0 = mBase + lr;
        const int b0 = m0 & 63;
        const int t0 = m0 >> 6;
        const float* Aptr = A + (size_t)(b0 * TT + t0) * NN + lk;
        const float* Bptr = Wih + (size_t)(nBase + lr) * NN + lk;

        ull acc2[8][4];
#pragma unroll
        for (int i = 0; i < 8; i++)
#pragma unroll
            for (int j = 0; j < 4; j++) acc2[i][j] = 0ull;

        for (int kt = 0; kt < NN; kt += 16) {
            const float4 a0 = *(const float4*)(Aptr + kt);
            const float4 a1 = *(const float4*)(Aptr + NN + kt);   // t0+1 row
            const float4 b0v = *(const float4*)(Bptr + kt);
            const float4 b1v = *(const float4*)(Bptr + 64 * NN + kt);
            __syncthreads();
            As[lk + 0][lr] = a0.x; As[lk + 1][lr] = a0.y; As[lk + 2][lr] = a0.z; As[lk + 3][lr] = a0.w;
            As[lk + 0][64 + lr] = a1.x; As[lk + 1][64 + lr] = a1.y; As[lk + 2][64 + lr] = a1.z; As[lk + 3][64 + lr] = a1.w;
            Bs[lk + 0][lr] = b0v.x; Bs[lk + 1][lr] = b0v.y; Bs[lk + 2][lr] = b0v.z; Bs[lk + 3][lr] = b0v.w;
            Bs[lk + 0][64 + lr] = b1v.x; Bs[lk + 1][64 + lr] = b1v.y; Bs[lk + 2][64 + lr] = b1v.z; Bs[lk + 3][64 + lr] = b1v.w;
            __syncthreads();
#pragma unroll
            for (int k = 0; k < 16; k++) {
                float af[8];
                *(float4*)&af[0] = *(const float4*)&As[k][ty * 4];
                *(float4*)&af[4] = *(const float4*)&As[k][64 + ty * 4];
                ull b2[4];
                *(uint4*)&b2[0] = *(const uint4*)&Bs[k][tx * 4];
                *(uint4*)&b2[2] = *(const uint4*)&Bs[k][64 + tx * 4];
#pragma unroll
                for (int i = 0; i < 8; i++) {
                    const ull ad = dup2(af[i]);
#pragma unroll
                    for (int j = 0; j < 4; j++) fma2(acc2[i][j], ad, b2[j]);
                }
            }
        }

        float bias[8];
#pragma unroll
        for (int j = 0; j < 8; j++) {
            int col = nBase + ((j < 4) ? (tx * 4 + j) : (64 + tx * 4 + (j - 4)));
            bias[j] = __ldg(&bih[col]);
        }
#pragma unroll
        for (int i = 0; i < 8; i++) {
            float a[8];
#pragma unroll
            for (int j = 0; j < 4; j++) {
                const float2 v = unpack2(acc2[i][j]);
                a[2 * j] = v.x; a[2 * j + 1] = v.y;
            }
            int row = mBase + ((i < 4) ? (ty * 4 + i) : (64 + ty * 4 + (i - 4)));
            float* cp = C + (size_t)row * G3 + nBase;
            *(float4*)(cp + tx * 4) =
                make_float4(a[0] + bias[0], a[1] + bias[1], a[2] + bias[2], a[3] + bias[3]);
            *(float4*)(cp + 64 + tx * 4) =
                make_float4(a[4] + bias[4], a[5] + bias[5], a[6] + bias[6], a[7] + bias[7]);
        }

        __threadfence();   // EACH thread: C stores -> gpu-scope visible
        __syncthreads();   // all threads fenced before publish
        if (tid == 0) {
            unsigned dummy;
            asm volatile("atom.release.gpu.global.add.u32 %0, [%1], %2;"
                         : "=r"(dummy) : "l"(&g_xdone[y].v), "r"(1u) : "memory");
        }
    }
}

// ---------------------------------------------------------------------------
// Scan role: EXACT R6/R8 shape. 128 CTAs x 256 threads, CTA owns 4 n-cols x
// 64 batches. thread=(kq 0..3, nn 0..3, b4 0..15): 128-k chunk, 4 batches,
// f32x2 -> 6 FFMA2/k. W pre-duplicated in SMEM. h via L1 (4x nn reuse);
// one IVALL/step. Step t gated on g_xdone[t>>1]==12 (acquire by tid0+bar).
// x loads PLAIN (writers are concurrent peer CTAs; RO path illegal).
// ---------------------------------------------------------------------------
__device__ void gru_scan(char* pool,
                         const float* __restrict__ Whh,
                         const float* __restrict__ bhh,
                         float* __restrict__ out) {
    ull   (*wsd)[514]     = (ull(*)[514])(pool + OFF_WSD);      // [12][514]
    float (*xs)[4][64]    = (float(*)[4][64])(pool + OFF_XS);   // [3][4][64]
    ull   (*red)[3][4][32]= (ull(*)[3][4][32])(pool + OFF_RED); // [4][3][4][32]
    float (*hs)[64]       = (float(*)[64])(pool + OFF_HS);      // [4][64]

    const int tid = threadIdx.x;
    const int n0  = blockIdx.x * 4;
    const int kq  = tid >> 6;
    const int nn  = (tid >> 4) & 3;
    const int b4  = tid & 15;

    // Load + duplicate W_hh slice once
    for (int i = tid; i < 12 * 512; i += 256) {
        const int row = i >> 9;            // gate*4 + jn
        const int k   = i & 511;
        const int gate = row >> 2;
        const int jn   = row & 3;
        wsd[row][k] = dup2(__ldg(&Whh[(size_t)(gate * NN + n0 + jn) * NN + k]));
    }

    // Epilogue biases (tid<128: en = tid>>5)
    float bhr = 0.f, bhz = 0.f, bhn = 0.f;
    if (tid < 128) {
        const int en = tid >> 5;
        bhr = __ldg(&bhh[n0 + en]);
        bhz = __ldg(&bhh[NN + n0 + en]);
        bhn = __ldg(&bhh[2 * NN + n0 + en]);
    }

    const ull* wr = &wsd[nn][kq * 128];
    const ull* wz = &wsd[4 + nn][kq * 128];
    const ull* wn = &wsd[8 + nn][kq * 128];
    __syncthreads();

    for (int t = 0; t < TT; t++) {
        const float* __restrict__ hcur = g_ht[t & 1];
        float*       __restrict__ hnxt = g_ht[(t & 1) ^ 1];

        // Gate on xproj progress for this t-slice (usually already set)
        if (tid == 0) {
            const int y = t >> 1;
            unsigned d;
            while (true) {
                asm volatile("ld.acquire.gpu.global.u32 %0, [%1];"
                             : "=r"(d) : "l"(&g_xdone[y].v) : "memory");
                if (d >= (unsigned)XT) break;
                __nanosleep(64);
            }
        }
        __syncthreads();

        // Stage x_proj[t, :, slice] — PLAIN float4 loads (concurrent writers)
        if (tid < 192) {
            const int gate = tid >> 6;
            const int b    = tid & 63;
            const float4 xv = *(const float4*)(
                g_xproj + (size_t)(t * BB + b) * G3 + gate * NN + n0);
            xs[gate][0][b] = xv.x; xs[gate][1][b] = xv.y;
            xs[gate][2][b] = xv.z; xs[gate][3][b] = xv.w;
        }

        // Mainloop: 128-k chunk, 4 batches (f32x2), L1-cached h (4x reuse)
        ull ar01 = 0ull, ar23 = 0ull;
        ull az01 = 0ull, az23 = 0ull;
        ull an01 = 0ull, an23 = 0ull;
        const float* hk = hcur + kq * 128 * BB + b4 * 4;
#pragma unroll 8
        for (int k = 0; k < 128; k++) {
            const ulonglong2 hv = *(const ulonglong2*)(hk + (size_t)k * BB);
            const ull w0 = wr[k];
            const ull w1 = wz[k];
            const ull w2 = wn[k];
            fma2(ar01, hv.x, w0); fma2(ar23, hv.y, w0);
            fma2(az01, hv.x, w1); fma2(az23, hv.y, w1);
            fma2(an01, hv.x, w2); fma2(an23, hv.y, w2);
        }
        *(ulonglong2*)&red[kq][0][nn][2 * b4] = make_ulonglong2(ar01, ar23);
        *(ulonglong2*)&red[kq][1][nn][2 * b4] = make_ulonglong2(az01, az23);
        *(ulonglong2*)&red[kq][2][nn][2 * b4] = make_ulonglong2(an01, an23);
        __syncthreads();

        // Epilogue: 128 threads, 2 batches each; writes transposed h directly
        if (tid < 128) {
            const int en = tid >> 5;    // n-col 0..3
            const int eb = tid & 31;    // batch pair
            ull sr = red[0][0][en][eb];
            ull sz = red[0][1][en][eb];
            ull sq = red[0][2][en][eb];
#pragma unroll
            for (int q = 1; q < 4; q++) {
                add2(sr, red[q][0][en][eb]);
                add2(sz, red[q][1][en][eb]);
                add2(sq, red[q][2][en][eb]);
            }
            const float2 arf = unpack2(sr);
            const float2 azf = unpack2(sz);
            const float2 aqf = unpack2(sq);
            const float2 hp = *(const float2*)(hcur + (n0 + en) * BB + eb * 2);
            const float2 xr = *(const float2*)&xs[0][en][eb * 2];
            const float2 xz = *(const float2*)&xs[1][en][eb * 2];
            const float2 xn = *(const float2*)&xs[2][en][eb * 2];

            const float r0  = 1.0f / (1.0f + __expf(-(xr.x + arf.x + bhr)));
            const float z0  = 1.0f / (1.0f + __expf(-(xz.x + azf.x + bhz)));
            const float n0v = tanhf(xn.x + r0 * (aqf.x + bhn));
            const float h0  = (1.0f - z0) * n0v + z0 * hp.x;

            const float r1  = 1.0f / (1.0f + __expf(-(xr.y + arf.y + bhr)));
            const float z1  = 1.0f / (1.0f + __expf(-(xz.y + azf.y + bhz)));
            const float n1v = tanhf(xn.y + r1 * (aqf.y + bhn));
            const float h1  = (1.0f - z1) * n1v + z1 * hp.y;

            __stcg((float2*)(hnxt + (n0 + en) * BB + eb * 2), make_float2(h0, h1));
            hs[en][eb * 2 + 0] = h0;
            hs[en][eb * 2 + 1] = h1;
        }
        __syncthreads();   // hnxt + hs complete; safe to arrive at barrier

        // Out-writeback overlaps the barrier wait (out is never re-read).
        if (tid < 64) {
            const int b = tid;
            __stcg((float4*)(out + (size_t)(b * TT + t) * NN + n0),
                   make_float4(hs[0][b], hs[1][b], hs[2][b], hs[3][b]));
        }

        // 128-CTA flat barrier (R6-proven): acq_rel arrival orders the stcg
        // h-stores (via bar.sync causality); release-publish; acquire-poll;
        // one acquire fence refreshes L1 h lines.
        if (t < TT - 1) {
            if (tid == 0) {
                const unsigned target = (unsigned)(t + 1);
                unsigned arrived;
                asm volatile("atom.acq_rel.gpu.global.add.u32 %0, [%1], %2;"
                             : "=r"(arrived) : "l"(&g_cnt.v), "r"(1u) : "memory");
                if (arrived + 1u == target * (unsigned)SCAN_CTAS) {
                    asm volatile("st.release.gpu.global.u32 [%0], %1;"
                                 :: "l"(&g_gen.v), "r"(target) : "memory");
                } else {
                    unsigned g;
                    while (true) {
                        asm volatile("ld.acquire.gpu.global.u32 %0, [%1];"
                                     : "=r"(g) : "l"(&g_gen.v) : "memory");
                        if (g >= target) break;
                        __nanosleep(32);
                    }
                }
            }
            __syncthreads();
            __threadfence();   // acquire: CCTL.IVALL so L1 h lines refresh
        }
    }
}

// ---------------------------------------------------------------------------
// Fused kernel, 2 CTAs/SM: CTAs 0..127 = scan (R6 shape), 128..255 = workers.
// __launch_bounds__(256,2) caps regs at 128 -> occupancy 2 -> all 256 CTAs
// co-resident in wave 1 -> scan barrier is deadlock-free; workers terminate.
// ---------------------------------------------------------------------------
__global__ void __launch_bounds__(256, 2) fused_kernel(
    const float* __restrict__ h_enc,
    const float* __restrict__ Wih,
    const float* __restrict__ Whh,
    const float* __restrict__ bih,
    const float* __restrict__ bhh,
    float* __restrict__ xproj,
    float* __restrict__ out) {
    extern __shared__ char pool[];
    if (blockIdx.x < SCAN_CTAS) {
        gru_scan(pool, Whh, bhh, out);
    } else {
        xproj_worker(pool, blockIdx.x - SCAN_CTAS, h_enc, Wih, bih, xproj);
    }
}

// ---------------------------------------------------------------------------
// Launch
// ---------------------------------------------------------------------------
extern "C" void kernel_launch(void* const* d_in, const int* in_sizes, int n_in,
                              void* d_out, int out_size) {
    const float* h_enc = (const float*)d_in[0];
    const float* W_ih  = (const float*)d_in[1];
    const float* W_hh  = (const float*)d_in[2];
    const float* b_ih  = (const float*)d_in[3];
    const float* b_hh  = (const float*)d_in[4];
    float* out = (float*)d_out;

    float* xproj_ptr = nullptr;
    cudaGetSymbolAddress((void**)&xproj_ptr, g_xproj);

    cudaFuncSetAttribute(fused_kernel,
                         cudaFuncAttributeMaxDynamicSharedMemorySize, SMEM_POOL);

    init_kernel<<<64, 256>>>();
    fused_kernel<<<TOTAL_CTAS, 256, SMEM_POOL>>>(
        h_enc, W_ih, W_hh, b_ih, b_hh, xproj_ptr, out);
}